// round 2
// baseline (speedup 1.0000x reference)
#include <cuda_runtime.h>
#include <math.h>

#define EMB    1024
#define HEADS  16
#define HD     64
#define BATCH  16
#define SEQ    1024
#define MTOT   (BATCH * SEQ)   // 16384

// ---------------------------------------------------------------------------
// Scratch (device globals; allocation is forbidden in kernel_launch)
// ---------------------------------------------------------------------------
__device__ float g_q[BATCH * HEADS * SEQ * HD];    // [B,H,P,D]  64 MB
__device__ float g_k[BATCH * HEADS * SEQ * HD];    // [B,H,P,D]  64 MB
__device__ float g_v[BATCH * HEADS * SEQ * HD];    // [B,H,P,D]  64 MB
__device__ float g_ctx[MTOT * EMB];                // [B*P, E]   64 MB

// ---------------------------------------------------------------------------
// SGEMM (NT): C[m,n] = sum_k A[m,k] * W[n,k] + bias[n]
// Tile 128x128, K-step 8, 256 threads, 8x8 per-thread microtile.
// Software-pipelined: next global tile prefetched into registers while
// computing current smem tile; double-buffered smem; ONE barrier per K-iter.
// scatter==1: write C[m,n] to out laid out as [B,H,P,D] (m=b*P+p, n=h*64+d)
// scatter==0: write to out[m*EMB + n]
// ---------------------------------------------------------------------------
__global__ __launch_bounds__(256)
void sgemm_nt(const float* __restrict__ A, const float* __restrict__ W,
              const float* __restrict__ bias, float* __restrict__ out,
              int scatter)
{
    __shared__ float As[2][8][128];
    __shared__ float Ws[2][8][128];

    const int tid  = threadIdx.x;
    const int row0 = blockIdx.y * 128;
    const int col0 = blockIdx.x * 128;

    // loader mapping: each thread loads one float4 of A and one of W per tile
    const int lr = tid >> 1;          // 0..127 (tile row)
    const int lk = (tid & 1) * 4;     // 0 or 4 (k offset)
    const float* Ap = A + (size_t)(row0 + lr) * EMB + lk;
    const float* Wp = W + (size_t)(col0 + lr) * EMB + lk;

    const int ty = tid >> 4;          // 0..15 -> C rows ty*8..ty*8+7
    const int tx = tid & 15;          // 0..15 -> C cols tx*8..tx*8+7

    float acc[8][8];
    #pragma unroll
    for (int i = 0; i < 8; i++)
        #pragma unroll
        for (int j = 0; j < 8; j++) acc[i][j] = 0.0f;

    // prologue: tile 0 -> buffer 0
    float4 av = *(const float4*)(Ap);
    float4 wv = *(const float4*)(Wp);
    As[0][lk + 0][lr] = av.x;  As[0][lk + 1][lr] = av.y;
    As[0][lk + 2][lr] = av.z;  As[0][lk + 3][lr] = av.w;
    Ws[0][lk + 0][lr] = wv.x;  Ws[0][lk + 1][lr] = wv.y;
    Ws[0][lk + 2][lr] = wv.z;  Ws[0][lk + 3][lr] = wv.w;
    __syncthreads();

    int buf = 0;
    for (int kt = 0; kt < EMB; kt += 8) {
        const bool more = (kt + 8 < EMB);
        if (more) {                       // prefetch next tile into registers
            av = *(const float4*)(Ap + kt + 8);
            wv = *(const float4*)(Wp + kt + 8);
        }

        #pragma unroll
        for (int k = 0; k < 8; k++) {
            float af[8], wf[8];
            #pragma unroll
            for (int i = 0; i < 8; i++) af[i] = As[buf][k][ty * 8 + i];
            #pragma unroll
            for (int j = 0; j < 8; j++) wf[j] = Ws[buf][k][tx * 8 + j];
            #pragma unroll
            for (int i = 0; i < 8; i++)
                #pragma unroll
                for (int j = 0; j < 8; j++)
                    acc[i][j] = fmaf(af[i], wf[j], acc[i][j]);
        }

        if (more) {
            const int nb = buf ^ 1;
            As[nb][lk + 0][lr] = av.x;  As[nb][lk + 1][lr] = av.y;
            As[nb][lk + 2][lr] = av.z;  As[nb][lk + 3][lr] = av.w;
            Ws[nb][lk + 0][lr] = wv.x;  Ws[nb][lk + 1][lr] = wv.y;
            Ws[nb][lk + 2][lr] = wv.z;  Ws[nb][lk + 3][lr] = wv.w;
            __syncthreads();
            buf = nb;
        }
    }

    // epilogue
    float bj[8];
    #pragma unroll
    for (int j = 0; j < 8; j++) bj[j] = bias[col0 + tx * 8 + j];

    #pragma unroll
    for (int i = 0; i < 8; i++) {
        const int m = row0 + ty * 8 + i;
        #pragma unroll
        for (int j = 0; j < 8; j++) {
            const int n = col0 + tx * 8 + j;
            const float v = acc[i][j] + bj[j];
            if (scatter) {
                const int b = m >> 10, p = m & 1023;
                const int h = n >> 6,  d = n & 63;
                out[((size_t)((b * HEADS + h) * SEQ + p)) * HD + d] = v;
            } else {
                out[(size_t)m * EMB + n] = v;
            }
        }
    }
}

// ---------------------------------------------------------------------------
// Flash attention, fp32. One thread owns one full q row (64 regs) and its
// output accumulator (64 regs) -> softmax state is entirely thread-local.
// K/V tiles of 32 keys staged in smem; reads are warp-broadcast.
// scores scale = 1/sqrt(P) = 1/32 (per reference!)
// ---------------------------------------------------------------------------
__global__ __launch_bounds__(128)
void flash_attn()
{
    __shared__ float Ks[32][64];
    __shared__ float Vs[32][64];

    const int bh  = blockIdx.y;                      // 0..255  (b*16 + h)
    const int p   = blockIdx.x * 128 + threadIdx.x;  // q row within sequence
    const float scale = 0.03125f;                    // 1/32

    const float* qp = g_q + ((size_t)bh * SEQ + p) * HD;
    float qr[64];
    #pragma unroll
    for (int i = 0; i < 16; i++) {
        float4 t = ((const float4*)qp)[i];
        qr[4 * i + 0] = t.x; qr[4 * i + 1] = t.y;
        qr[4 * i + 2] = t.z; qr[4 * i + 3] = t.w;
    }

    float acc[64];
    #pragma unroll
    for (int d = 0; d < 64; d++) acc[d] = 0.0f;
    float m = -1e30f, l = 0.0f;

    for (int kt = 0; kt < SEQ; kt += 32) {
        const float4* kb = (const float4*)(g_k + ((size_t)bh * SEQ + kt) * HD);
        const float4* vb = (const float4*)(g_v + ((size_t)bh * SEQ + kt) * HD);
        __syncthreads();
        #pragma unroll
        for (int i = 0; i < 4; i++) {
            const int idx = threadIdx.x + i * 128;   // 0..511 float4s
            ((float4*)Ks)[idx] = kb[idx];
            ((float4*)Vs)[idx] = vb[idx];
        }
        __syncthreads();

        float s[32];
        #pragma unroll
        for (int j = 0; j < 32; j++) {
            float d0 = 0.0f, d1 = 0.0f;
            #pragma unroll
            for (int d = 0; d < 64; d += 2) {
                d0 = fmaf(qr[d],     Ks[j][d],     d0);
                d1 = fmaf(qr[d + 1], Ks[j][d + 1], d1);
            }
            s[j] = (d0 + d1) * scale;
        }

        float smax = s[0];
        #pragma unroll
        for (int j = 1; j < 32; j++) smax = fmaxf(smax, s[j]);
        const float mn   = fmaxf(m, smax);
        const float corr = __expf(m - mn);
        m = mn;
        l *= corr;
        #pragma unroll
        for (int d = 0; d < 64; d++) acc[d] *= corr;

        #pragma unroll
        for (int j = 0; j < 32; j++) {
            const float pj = __expf(s[j] - m);
            l += pj;
            #pragma unroll
            for (int d = 0; d < 64; d++)
                acc[d] = fmaf(pj, Vs[j][d], acc[d]);
        }
    }

    const float inv = 1.0f / l;
    const int b = bh >> 4, h = bh & 15;
    float* op = g_ctx + ((size_t)(b * SEQ + p)) * EMB + h * HD;
    #pragma unroll
    for (int i = 0; i < 16; i++) {
        float4 t;
        t.x = acc[4 * i + 0] * inv; t.y = acc[4 * i + 1] * inv;
        t.z = acc[4 * i + 2] * inv; t.w = acc[4 * i + 3] * inv;
        ((float4*)op)[i] = t;
    }
}

// ---------------------------------------------------------------------------
// launch
// ---------------------------------------------------------------------------
extern "C" void kernel_launch(void* const* d_in, const int* in_sizes, int n_in,
                              void* d_out, int out_size)
{
    const float* x  = (const float*)d_in[0];
    const float* wq = (const float*)d_in[1];
    const float* bq = (const float*)d_in[2];
    const float* wk = (const float*)d_in[3];
    const float* bk = (const float*)d_in[4];
    const float* wv = (const float*)d_in[5];
    const float* bv = (const float*)d_in[6];
    const float* wo = (const float*)d_in[7];
    const float* bo = (const float*)d_in[8];
    float* out = (float*)d_out;

    float *qbuf, *kbuf, *vbuf, *cbuf;
    cudaGetSymbolAddress((void**)&qbuf, g_q);
    cudaGetSymbolAddress((void**)&kbuf, g_k);
    cudaGetSymbolAddress((void**)&vbuf, g_v);
    cudaGetSymbolAddress((void**)&cbuf, g_ctx);

    dim3 gGemm(EMB / 128, MTOT / 128);   // (8, 128)
    sgemm_nt<<<gGemm, 256>>>(x, wq, bq, qbuf, 1);
    sgemm_nt<<<gGemm, 256>>>(x, wk, bk, kbuf, 1);
    sgemm_nt<<<gGemm, 256>>>(x, wv, bv, vbuf, 1);

    dim3 gAttn(SEQ / 128, BATCH * HEADS);  // (8, 256)
    flash_attn<<<gAttn, 128>>>();

    sgemm_nt<<<gGemm, 256>>>(cbuf, wo, bo, out, 0);
}

// round 4
// speedup vs baseline: 1.0548x; 1.0548x over previous
#include <cuda_runtime.h>
#include <math.h>

#define EMB    1024
#define HEADS  16
#define HD     64
#define BATCH  16
#define SEQ    1024
#define MTOT   (BATCH * SEQ)   // 16384

// ---------------------------------------------------------------------------
// Scratch (device globals; allocation is forbidden in kernel_launch)
// ---------------------------------------------------------------------------
__device__ float g_q[BATCH * HEADS * SEQ * HD];    // [B,H,P,D]  64 MB
__device__ float g_k[BATCH * HEADS * SEQ * HD];    // [B,H,P,D]  64 MB
__device__ float g_v[BATCH * HEADS * SEQ * HD];    // [B,H,P,D]  64 MB
__device__ float g_ctx[MTOT * EMB];                // [B*P, E]   64 MB

// ---------------------------------------------------------------------------
// SGEMM (NT): C[m,n] = sum_k A[m,k] * W[n,k] + bias[n]
// Tile 128x128, K-step 16, 256 threads, 8x8 per-thread microtile.
// Software-pipelined (register prefetch), double-buffered smem,
// ONE barrier per 16-wide K-iteration (64 barriers total).
// scatter==1: write C[m,n] to out laid out as [B,H,P,D] (m=b*P+p, n=h*64+d)
// scatter==0: write to out[m*EMB + n]
// ---------------------------------------------------------------------------
__global__ __launch_bounds__(256)
void sgemm_nt(const float* __restrict__ A, const float* __restrict__ W,
              const float* __restrict__ bias, float* __restrict__ out,
              int scatter)
{
    __shared__ float As[2][16][128];
    __shared__ float Ws[2][16][128];

    const int tid  = threadIdx.x;
    const int row0 = blockIdx.y * 128;
    const int col0 = blockIdx.x * 128;

    // loader: each thread loads 2 float4 of A and 2 of W per 128x16 tile
    const int lr = tid >> 1;          // 0..127 (tile row)
    const int lk = (tid & 1) * 8;     // 0 or 8 (k offset, 8 consecutive k)
    const float* Ap = A + (size_t)(row0 + lr) * EMB + lk;
    const float* Wp = W + (size_t)(col0 + lr) * EMB + lk;

    const int ty = tid >> 4;          // 0..15 -> C rows ty*8..ty*8+7
    const int tx = tid & 15;          // 0..15 -> C cols tx*8..tx*8+7

    float acc[8][8];
    #pragma unroll
    for (int i = 0; i < 8; i++)
        #pragma unroll
        for (int j = 0; j < 8; j++) acc[i][j] = 0.0f;

    // prologue: tile 0 -> buffer 0
    float4 a0 = *(const float4*)(Ap + 0);
    float4 a1 = *(const float4*)(Ap + 4);
    float4 w0 = *(const float4*)(Wp + 0);
    float4 w1 = *(const float4*)(Wp + 4);
    As[0][lk + 0][lr] = a0.x; As[0][lk + 1][lr] = a0.y;
    As[0][lk + 2][lr] = a0.z; As[0][lk + 3][lr] = a0.w;
    As[0][lk + 4][lr] = a1.x; As[0][lk + 5][lr] = a1.y;
    As[0][lk + 6][lr] = a1.z; As[0][lk + 7][lr] = a1.w;
    Ws[0][lk + 0][lr] = w0.x; Ws[0][lk + 1][lr] = w0.y;
    Ws[0][lk + 2][lr] = w0.z; Ws[0][lk + 3][lr] = w0.w;
    Ws[0][lk + 4][lr] = w1.x; Ws[0][lk + 5][lr] = w1.y;
    Ws[0][lk + 6][lr] = w1.z; Ws[0][lk + 7][lr] = w1.w;
    __syncthreads();

    int buf = 0;
    for (int kt = 0; kt < EMB; kt += 16) {
        const bool more = (kt + 16 < EMB);
        if (more) {                   // prefetch next tile into registers
            a0 = *(const float4*)(Ap + kt + 16);
            a1 = *(const float4*)(Ap + kt + 20);
            w0 = *(const float4*)(Wp + kt + 16);
            w1 = *(const float4*)(Wp + kt + 20);
        }

        #pragma unroll
        for (int k = 0; k < 16; k++) {
            float af[8], wf[8];
            *(float4*)(af + 0) = *(const float4*)(&As[buf][k][ty * 8 + 0]);
            *(float4*)(af + 4) = *(const float4*)(&As[buf][k][ty * 8 + 4]);
            *(float4*)(wf + 0) = *(const float4*)(&Ws[buf][k][tx * 8 + 0]);
            *(float4*)(wf + 4) = *(const float4*)(&Ws[buf][k][tx * 8 + 4]);
            #pragma unroll
            for (int i = 0; i < 8; i++)
                #pragma unroll
                for (int j = 0; j < 8; j++)
                    acc[i][j] = fmaf(af[i], wf[j], acc[i][j]);
        }

        if (more) {
            const int nb = buf ^ 1;
            As[nb][lk + 0][lr] = a0.x; As[nb][lk + 1][lr] = a0.y;
            As[nb][lk + 2][lr] = a0.z; As[nb][lk + 3][lr] = a0.w;
            As[nb][lk + 4][lr] = a1.x; As[nb][lk + 5][lr] = a1.y;
            As[nb][lk + 6][lr] = a1.z; As[nb][lk + 7][lr] = a1.w;
            Ws[nb][lk + 0][lr] = w0.x; Ws[nb][lk + 1][lr] = w0.y;
            Ws[nb][lk + 2][lr] = w0.z; Ws[nb][lk + 3][lr] = w0.w;
            Ws[nb][lk + 4][lr] = w1.x; Ws[nb][lk + 5][lr] = w1.y;
            Ws[nb][lk + 6][lr] = w1.z; Ws[nb][lk + 7][lr] = w1.w;
            __syncthreads();
            buf = nb;
        }
    }

    // epilogue
    float bj[8];
    #pragma unroll
    for (int j = 0; j < 8; j++) bj[j] = bias[col0 + tx * 8 + j];

    #pragma unroll
    for (int i = 0; i < 8; i++) {
        const int m = row0 + ty * 8 + i;
        #pragma unroll
        for (int j = 0; j < 8; j++) {
            const int n = col0 + tx * 8 + j;
            const float v = acc[i][j] + bj[j];
            if (scatter) {
                const int b = m >> 10, p = m & 1023;
                const int h = n >> 6,  d = n & 63;
                out[((size_t)((b * HEADS + h) * SEQ + p)) * HD + d] = v;
            } else {
                out[(size_t)m * EMB + n] = v;
            }
        }
    }
}

// ---------------------------------------------------------------------------
// Flash attention, fp32. One thread owns one q row + accumulator in regs.
// ALL smem reads are explicit float4 (LDS.128, warp-broadcast, conflict-free)
// -> 4x fewer LDS instructions; FMA pipe becomes the binding resource.
// scores scale = 1/sqrt(P) = 1/32 (per reference!)
// ---------------------------------------------------------------------------
__global__ __launch_bounds__(128)
void flash_attn()
{
    __shared__ float Ks[32][64];
    __shared__ float Vs[32][64];

    const int bh  = blockIdx.y;                      // 0..255  (b*16 + h)
    const int p   = blockIdx.x * 128 + threadIdx.x;  // q row within sequence
    const float scale = 0.03125f;                    // 1/32

    const float* qp = g_q + ((size_t)bh * SEQ + p) * HD;
    float qr[64];
    #pragma unroll
    for (int i = 0; i < 16; i++) {
        float4 t = ((const float4*)qp)[i];
        qr[4 * i + 0] = t.x; qr[4 * i + 1] = t.y;
        qr[4 * i + 2] = t.z; qr[4 * i + 3] = t.w;
    }

    float acc[64];
    #pragma unroll
    for (int d = 0; d < 64; d++) acc[d] = 0.0f;
    float m = -1e30f, l = 0.0f;

    for (int kt = 0; kt < SEQ; kt += 32) {
        const float4* kb = (const float4*)(g_k + ((size_t)bh * SEQ + kt) * HD);
        const float4* vb = (const float4*)(g_v + ((size_t)bh * SEQ + kt) * HD);
        __syncthreads();
        #pragma unroll
        for (int i = 0; i < 4; i++) {
            const int idx = threadIdx.x + i * 128;   // 0..511 float4s
            ((float4*)Ks)[idx] = kb[idx];
            ((float4*)Vs)[idx] = vb[idx];
        }
        __syncthreads();

        // scores: q . K_j  with float4 smem reads
        float s[32];
        #pragma unroll
        for (int j = 0; j < 32; j++) {
            const float4* Krow = (const float4*)(&Ks[j][0]);
            float d0 = 0.0f, d1 = 0.0f, d2 = 0.0f, d3 = 0.0f;
            #pragma unroll
            for (int i = 0; i < 16; i++) {
                float4 kv = Krow[i];
                d0 = fmaf(qr[4 * i + 0], kv.x, d0);
                d1 = fmaf(qr[4 * i + 1], kv.y, d1);
                d2 = fmaf(qr[4 * i + 2], kv.z, d2);
                d3 = fmaf(qr[4 * i + 3], kv.w, d3);
            }
            s[j] = ((d0 + d1) + (d2 + d3)) * scale;
        }

        float smax = s[0];
        #pragma unroll
        for (int j = 1; j < 32; j++) smax = fmaxf(smax, s[j]);
        const float mn   = fmaxf(m, smax);
        const float corr = __expf(m - mn);
        m = mn;
        l *= corr;
        #pragma unroll
        for (int d = 0; d < 64; d++) acc[d] *= corr;

        // P @ V with float4 smem reads
        #pragma unroll
        for (int j = 0; j < 32; j++) {
            const float pj = __expf(s[j] - m);
            l += pj;
            const float4* Vrow = (const float4*)(&Vs[j][0]);
            #pragma unroll
            for (int i = 0; i < 16; i++) {
                float4 vv = Vrow[i];
                acc[4 * i + 0] = fmaf(pj, vv.x, acc[4 * i + 0]);
                acc[4 * i + 1] = fmaf(pj, vv.y, acc[4 * i + 1]);
                acc[4 * i + 2] = fmaf(pj, vv.z, acc[4 * i + 2]);
                acc[4 * i + 3] = fmaf(pj, vv.w, acc[4 * i + 3]);
            }
        }
    }

    const float inv = 1.0f / l;
    const int b = bh >> 4, h = bh & 15;
    float* op = g_ctx + ((size_t)(b * SEQ + p)) * EMB + h * HD;
    #pragma unroll
    for (int i = 0; i < 16; i++) {
        float4 t;
        t.x = acc[4 * i + 0] * inv; t.y = acc[4 * i + 1] * inv;
        t.z = acc[4 * i + 2] * inv; t.w = acc[4 * i + 3] * inv;
        ((float4*)op)[i] = t;
    }
}

// ---------------------------------------------------------------------------
// launch
// ---------------------------------------------------------------------------
extern "C" void kernel_launch(void* const* d_in, const int* in_sizes, int n_in,
                              void* d_out, int out_size)
{
    const float* x  = (const float*)d_in[0];
    const float* wq = (const float*)d_in[1];
    const float* bq = (const float*)d_in[2];
    const float* wk = (const float*)d_in[3];
    const float* bk = (const float*)d_in[4];
    const float* wv = (const float*)d_in[5];
    const float* bv = (const float*)d_in[6];
    const float* wo = (const float*)d_in[7];
    const float* bo = (const float*)d_in[8];
    float* out = (float*)d_out;

    float *qbuf, *kbuf, *vbuf, *cbuf;
    cudaGetSymbolAddress((void**)&qbuf, g_q);
    cudaGetSymbolAddress((void**)&kbuf, g_k);
    cudaGetSymbolAddress((void**)&vbuf, g_v);
    cudaGetSymbolAddress((void**)&cbuf, g_ctx);

    dim3 gGemm(EMB / 128, MTOT / 128);   // (8, 128)
    sgemm_nt<<<gGemm, 256>>>(x, wq, bq, qbuf, 1);
    sgemm_nt<<<gGemm, 256>>>(x, wk, bk, kbuf, 1);
    sgemm_nt<<<gGemm, 256>>>(x, wv, bv, vbuf, 1);

    dim3 gAttn(SEQ / 128, BATCH * HEADS);  // (8, 256)
    flash_attn<<<gAttn, 128>>>();

    sgemm_nt<<<gGemm, 256>>>(cbuf, wo, bo, out, 0);
}

// round 5
// speedup vs baseline: 1.1178x; 1.0597x over previous
#include <cuda_runtime.h>
#include <math.h>

#define EMB    1024
#define HEADS  16
#define HD     64
#define BATCH  16
#define SEQ    1024
#define MTOT   (BATCH * SEQ)   // 16384

// ---------------------------------------------------------------------------
// Scratch (device globals; allocation is forbidden in kernel_launch)
// ---------------------------------------------------------------------------
__device__ float g_q[BATCH * HEADS * SEQ * HD];    // [B,H,P,D]  64 MB
__device__ float g_k[BATCH * HEADS * SEQ * HD];    // [B,H,P,D]  64 MB
__device__ float g_v[BATCH * HEADS * SEQ * HD];    // [B,H,P,D]  64 MB
__device__ float g_ctx[MTOT * EMB];                // [B*P, E]   64 MB

// ---------------------------------------------------------------------------
// SGEMM (NT): C[m,n] = sum_k A[m,k] * W[n,k] + bias[n]
// Tile 128x128, K-step 16, 256 threads, 8x8 per-thread microtile.
// Software-pipelined (register prefetch), double-buffered smem,
// ONE barrier per 16-wide K-iteration.
// ---------------------------------------------------------------------------
__global__ __launch_bounds__(256)
void sgemm_nt(const float* __restrict__ A, const float* __restrict__ W,
              const float* __restrict__ bias, float* __restrict__ out,
              int scatter)
{
    __shared__ float As[2][16][128];
    __shared__ float Ws[2][16][128];

    const int tid  = threadIdx.x;
    const int row0 = blockIdx.y * 128;
    const int col0 = blockIdx.x * 128;

    const int lr = tid >> 1;          // 0..127 (tile row)
    const int lk = (tid & 1) * 8;     // 0 or 8
    const float* Ap = A + (size_t)(row0 + lr) * EMB + lk;
    const float* Wp = W + (size_t)(col0 + lr) * EMB + lk;

    const int ty = tid >> 4;          // 0..15
    const int tx = tid & 15;          // 0..15

    float acc[8][8];
    #pragma unroll
    for (int i = 0; i < 8; i++)
        #pragma unroll
        for (int j = 0; j < 8; j++) acc[i][j] = 0.0f;

    float4 a0 = *(const float4*)(Ap + 0);
    float4 a1 = *(const float4*)(Ap + 4);
    float4 w0 = *(const float4*)(Wp + 0);
    float4 w1 = *(const float4*)(Wp + 4);
    As[0][lk + 0][lr] = a0.x; As[0][lk + 1][lr] = a0.y;
    As[0][lk + 2][lr] = a0.z; As[0][lk + 3][lr] = a0.w;
    As[0][lk + 4][lr] = a1.x; As[0][lk + 5][lr] = a1.y;
    As[0][lk + 6][lr] = a1.z; As[0][lk + 7][lr] = a1.w;
    Ws[0][lk + 0][lr] = w0.x; Ws[0][lk + 1][lr] = w0.y;
    Ws[0][lk + 2][lr] = w0.z; Ws[0][lk + 3][lr] = w0.w;
    Ws[0][lk + 4][lr] = w1.x; Ws[0][lk + 5][lr] = w1.y;
    Ws[0][lk + 6][lr] = w1.z; Ws[0][lk + 7][lr] = w1.w;
    __syncthreads();

    int buf = 0;
    for (int kt = 0; kt < EMB; kt += 16) {
        const bool more = (kt + 16 < EMB);
        if (more) {
            a0 = *(const float4*)(Ap + kt + 16);
            a1 = *(const float4*)(Ap + kt + 20);
            w0 = *(const float4*)(Wp + kt + 16);
            w1 = *(const float4*)(Wp + kt + 20);
        }

        #pragma unroll
        for (int k = 0; k < 16; k++) {
            float af[8], wf[8];
            *(float4*)(af + 0) = *(const float4*)(&As[buf][k][ty * 8 + 0]);
            *(float4*)(af + 4) = *(const float4*)(&As[buf][k][ty * 8 + 4]);
            *(float4*)(wf + 0) = *(const float4*)(&Ws[buf][k][tx * 8 + 0]);
            *(float4*)(wf + 4) = *(const float4*)(&Ws[buf][k][tx * 8 + 4]);
            #pragma unroll
            for (int i = 0; i < 8; i++)
                #pragma unroll
                for (int j = 0; j < 8; j++)
                    acc[i][j] = fmaf(af[i], wf[j], acc[i][j]);
        }

        if (more) {
            const int nb = buf ^ 1;
            As[nb][lk + 0][lr] = a0.x; As[nb][lk + 1][lr] = a0.y;
            As[nb][lk + 2][lr] = a0.z; As[nb][lk + 3][lr] = a0.w;
            As[nb][lk + 4][lr] = a1.x; As[nb][lk + 5][lr] = a1.y;
            As[nb][lk + 6][lr] = a1.z; As[nb][lk + 7][lr] = a1.w;
            Ws[nb][lk + 0][lr] = w0.x; Ws[nb][lk + 1][lr] = w0.y;
            Ws[nb][lk + 2][lr] = w0.z; Ws[nb][lk + 3][lr] = w0.w;
            Ws[nb][lk + 4][lr] = w1.x; Ws[nb][lk + 5][lr] = w1.y;
            Ws[nb][lk + 6][lr] = w1.z; Ws[nb][lk + 7][lr] = w1.w;
            __syncthreads();
            buf = nb;
        }
    }

    float bj[8];
    #pragma unroll
    for (int j = 0; j < 8; j++) bj[j] = bias[col0 + tx * 8 + j];

    #pragma unroll
    for (int i = 0; i < 8; i++) {
        const int m = row0 + ty * 8 + i;
        #pragma unroll
        for (int j = 0; j < 8; j++) {
            const int n = col0 + tx * 8 + j;
            const float v = acc[i][j] + bj[j];
            if (scatter) {
                const int b = m >> 10, p = m & 1023;
                const int h = n >> 6,  d = n & 63;
                out[((size_t)((b * HEADS + h) * SEQ + p)) * HD + d] = v;
            } else {
                out[(size_t)m * EMB + n] = v;
            }
        }
    }
}

// ---------------------------------------------------------------------------
// Flash attention, fp32, PAIRED-THREAD layout:
//   even/odd thread pair splits the 64-dim head: each thread owns 2 q rows x
//   its 32-dim half (q + acc in regs). Half dot-products combined with one
//   shfl.xor(1) per (row,key). Each loaded K/V float feeds 2 FMAs -> smem
//   traffic per FMA halved vs one-thread-one-row.
// K/V tiles: 16 keys, smem rows padded to 72 floats (half1 at +36 floats)
// so the pair's two LDS.128 addresses land on disjoint banks.
// scores scale = 1/sqrt(P) = 1/32 (per reference!)
// ---------------------------------------------------------------------------
#define KT     16            // keys per tile
#define KPAD   72            // floats per padded smem row
#define HOFF2  36            // float offset of d[32:64) half within a row

__global__ __launch_bounds__(128)
void flash_attn()
{
    __shared__ float Ks[KT * KPAD];
    __shared__ float Vs[KT * KPAD];

    const int tid  = threadIdx.x;
    const int half = tid & 1;                 // 0: d[0,32), 1: d[32,64)
    const int pr   = tid >> 1;                // 0..63 pair index
    const int bh   = blockIdx.y;              // 0..255 (b*16+h)
    const int r0   = blockIdx.x * 128 + pr * 2;   // this pair's q rows r0, r0+1
    const float scale = 0.03125f;             // 1/32
    const int hoff = half * 32;               // global d offset of my half
    const int soff = half * HOFF2;            // smem float offset of my half

    // load q: 2 rows x my 32-dim half
    float qr[2][32];
    #pragma unroll
    for (int r = 0; r < 2; r++) {
        const float4* qp = (const float4*)(g_q + ((size_t)bh * SEQ + r0 + r) * HD + hoff);
        #pragma unroll
        for (int i = 0; i < 8; i++) {
            float4 t4 = qp[i];
            qr[r][4*i+0] = t4.x; qr[r][4*i+1] = t4.y;
            qr[r][4*i+2] = t4.z; qr[r][4*i+3] = t4.w;
        }
    }

    float acc[2][32];
    #pragma unroll
    for (int r = 0; r < 2; r++)
        #pragma unroll
        for (int d = 0; d < 32; d++) acc[r][d] = 0.0f;
    float m0 = -1e30f, m1 = -1e30f, l0 = 0.0f, l1 = 0.0f;

    for (int kt = 0; kt < SEQ; kt += KT) {
        // stage 16 keys x 64 floats of K and V (256 float4 each); thread
        // loads float4 #tid and #tid+128, storing into the padded layout.
        __syncthreads();
        #pragma unroll
        for (int u = 0; u < 2; u++) {
            const int idx = tid + u * 128;        // 0..255
            const int key = idx >> 4;             // 0..15
            const int c   = idx & 15;             // float4 within 64-float row
            const int dst = key * KPAD + c * 4 + (c >= 8 ? 4 : 0);
            const size_t src = ((size_t)bh * SEQ + kt + key) * HD + c * 4;
            *(float4*)(Ks + dst) = *(const float4*)(g_k + src);
            *(float4*)(Vs + dst) = *(const float4*)(g_v + src);
        }
        __syncthreads();

        // scores: half-dots + pair combine via shfl.xor(1)
        float s0[KT], s1[KT];
        #pragma unroll
        for (int j = 0; j < KT; j++) {
            const float4* Kr = (const float4*)(Ks + j * KPAD + soff);
            float a0 = 0.0f, a1 = 0.0f, b0 = 0.0f, b1 = 0.0f;
            #pragma unroll
            for (int i = 0; i < 8; i++) {
                float4 kv = Kr[i];
                a0 = fmaf(qr[0][4*i+0], kv.x, a0);
                a1 = fmaf(qr[0][4*i+1], kv.y, a1);
                a0 = fmaf(qr[0][4*i+2], kv.z, a0);
                a1 = fmaf(qr[0][4*i+3], kv.w, a1);
                b0 = fmaf(qr[1][4*i+0], kv.x, b0);
                b1 = fmaf(qr[1][4*i+1], kv.y, b1);
                b0 = fmaf(qr[1][4*i+2], kv.z, b0);
                b1 = fmaf(qr[1][4*i+3], kv.w, b1);
            }
            const float pa = a0 + a1;            // my half-dot, row 0
            const float pb = b0 + b1;            // my half-dot, row 1
            const float qa = __shfl_xor_sync(0xffffffffu, pa, 1);
            const float qb = __shfl_xor_sync(0xffffffffu, pb, 1);
            s0[j] = (pa + qa) * scale;           // commutative: identical in pair
            s1[j] = (pb + qb) * scale;
        }

        // online softmax update (both pair threads compute identical m/l)
        float t0 = s0[0], t1 = s1[0];
        #pragma unroll
        for (int j = 1; j < KT; j++) { t0 = fmaxf(t0, s0[j]); t1 = fmaxf(t1, s1[j]); }
        const float n0 = fmaxf(m0, t0), n1 = fmaxf(m1, t1);
        const float c0 = __expf(m0 - n0), c1 = __expf(m1 - n1);
        m0 = n0; m1 = n1;
        l0 *= c0; l1 *= c1;
        #pragma unroll
        for (int d = 0; d < 32; d++) { acc[0][d] *= c0; acc[1][d] *= c1; }

        // P @ V on my half
        #pragma unroll
        for (int j = 0; j < KT; j++) {
            const float p0 = __expf(s0[j] - m0);
            const float p1 = __expf(s1[j] - m1);
            l0 += p0; l1 += p1;
            const float4* Vr = (const float4*)(Vs + j * KPAD + soff);
            #pragma unroll
            for (int i = 0; i < 8; i++) {
                float4 vv = Vr[i];
                acc[0][4*i+0] = fmaf(p0, vv.x, acc[0][4*i+0]);
                acc[0][4*i+1] = fmaf(p0, vv.y, acc[0][4*i+1]);
                acc[0][4*i+2] = fmaf(p0, vv.z, acc[0][4*i+2]);
                acc[0][4*i+3] = fmaf(p0, vv.w, acc[0][4*i+3]);
                acc[1][4*i+0] = fmaf(p1, vv.x, acc[1][4*i+0]);
                acc[1][4*i+1] = fmaf(p1, vv.y, acc[1][4*i+1]);
                acc[1][4*i+2] = fmaf(p1, vv.z, acc[1][4*i+2]);
                acc[1][4*i+3] = fmaf(p1, vv.w, acc[1][4*i+3]);
            }
        }
    }

    const float i0 = 1.0f / l0, i1 = 1.0f / l1;
    const int b = bh >> 4, h = bh & 15;
    #pragma unroll
    for (int r = 0; r < 2; r++) {
        const float inv = r ? i1 : i0;
        float4* op = (float4*)(g_ctx + ((size_t)(b * SEQ + r0 + r)) * EMB + h * HD + hoff);
        #pragma unroll
        for (int i = 0; i < 8; i++) {
            float4 t4;
            t4.x = acc[r][4*i+0] * inv; t4.y = acc[r][4*i+1] * inv;
            t4.z = acc[r][4*i+2] * inv; t4.w = acc[r][4*i+3] * inv;
            op[i] = t4;
        }
    }
}

// ---------------------------------------------------------------------------
// launch
// ---------------------------------------------------------------------------
extern "C" void kernel_launch(void* const* d_in, const int* in_sizes, int n_in,
                              void* d_out, int out_size)
{
    const float* x  = (const float*)d_in[0];
    const float* wq = (const float*)d_in[1];
    const float* bq = (const float*)d_in[2];
    const float* wk = (const float*)d_in[3];
    const float* bk = (const float*)d_in[4];
    const float* wv = (const float*)d_in[5];
    const float* bv = (const float*)d_in[6];
    const float* wo = (const float*)d_in[7];
    const float* bo = (const float*)d_in[8];
    float* out = (float*)d_out;

    float *qbuf, *kbuf, *vbuf, *cbuf;
    cudaGetSymbolAddress((void**)&qbuf, g_q);
    cudaGetSymbolAddress((void**)&kbuf, g_k);
    cudaGetSymbolAddress((void**)&vbuf, g_v);
    cudaGetSymbolAddress((void**)&cbuf, g_ctx);

    dim3 gGemm(EMB / 128, MTOT / 128);   // (8, 128)
    sgemm_nt<<<gGemm, 256>>>(x, wq, bq, qbuf, 1);
    sgemm_nt<<<gGemm, 256>>>(x, wk, bk, kbuf, 1);
    sgemm_nt<<<gGemm, 256>>>(x, wv, bv, vbuf, 1);

    dim3 gAttn(SEQ / 128, BATCH * HEADS);  // (8, 256)
    flash_attn<<<gAttn, 128>>>();

    sgemm_nt<<<gGemm, 256>>>(cbuf, wo, bo, out, 0);
}